// round 4
// baseline (speedup 1.0000x reference)
#include <cuda_runtime.h>
#include <math.h>

#define B    8
#define S    256
#define H    768
#define P    256
#define NE   20000
#define NT   100000
#define NR   200
#define HOPS 3

// ---------------- scratch (device globals) ----------------
__device__ float g_wvp[H];
__device__ float g_slogit[B * S];
__device__ float g_ptr[B * S];
__device__ float g_D[B * H];
__device__ float g_Rlog[B * HOPS * NR];
__device__ float g_Clog[B * HOPS * 2];
__device__ float g_R[B * HOPS * NR];
__device__ float g_CS[B * HOPS * 2];
__device__ float g_LD[B * H];
__device__ float g_walkraw[B * HOPS * NE];
__device__ float g_sumacc[B * HOPS];       // raw sums (atomic acc)
__device__ float g_scores[B * NE];
__device__ float g_mx[B * HOPS];           // softmax max per (b,hop)
__device__ float g_esum[B * HOPS];         // exp-sum per (b,hop)
__device__ float g_ebuf[B * HOPS * NE];    // exp values

// ---------------- helpers ----------------
__device__ __forceinline__ float warpSum(float v) {
    #pragma unroll
    for (int o = 16; o; o >>= 1) v += __shfl_xor_sync(0xffffffffu, v, o);
    return v;
}
__device__ __forceinline__ float warpMax(float v) {
    #pragma unroll
    for (int o = 16; o; o >>= 1) v = fmaxf(v, __shfl_xor_sync(0xffffffffu, v, o));
    return v;
}
__device__ __forceinline__ void atomicMaxF(float* addr, float val) {
    int old = __float_as_int(*addr);
    while (__int_as_float(old) < val) {
        int assumed = old;
        old = atomicCAS((int*)addr, assumed, __float_as_int(val));
        if (old == assumed) break;
    }
}

// ---------------- kernels ----------------

// zero all atomic-accumulated scratch; first 768 warps compute wvp
__global__ void k_init(const float* __restrict__ Wv, const float* __restrict__ Wp) {
    int idx = blockIdx.x * blockDim.x + threadIdx.x;          // 1875*256
    if (idx < B * HOPS * NE) g_walkraw[idx] = 0.f;
    if (idx < B * H) { g_D[idx] = 0.f; g_LD[idx] = 0.f; }
    if (idx < B * HOPS * NR) g_Rlog[idx] = 0.f;
    if (idx < B * HOPS * 2) g_Clog[idx] = 0.f;
    if (idx < B * HOPS) { g_sumacc[idx] = 0.f; g_esum[idx] = 0.f; g_mx[idx] = -1e30f; }
    int warp = idx >> 5;
    int lane = threadIdx.x & 31;
    if (warp < H) {
        float acc = 0.f;
        #pragma unroll
        for (int p = lane; p < P; p += 32) acc += Wv[warp * P + p] * Wp[p];
        acc = warpSum(acc);
        if (lane == 0) g_wvp[warp] = acc;
    }
}

// slogit[b,s] = dot(lhs[b,s,:], wvp) — warp per row, 2048 warps
__global__ void k_logit(const float* __restrict__ lhs) {
    __shared__ float4 sw[H / 4];
    for (int i = threadIdx.x; i < H / 4; i += blockDim.x)
        sw[i] = ((const float4*)g_wvp)[i];
    __syncthreads();
    int warp = threadIdx.x >> 5, lane = threadIdx.x & 31;
    int row = blockIdx.x * 32 + warp;
    const float4* base = (const float4*)(lhs + (size_t)row * H);
    float acc = 0.f;
    #pragma unroll
    for (int it = 0; it < 6; it++) {
        int j = lane + it * 32;
        float4 v = base[j], w = sw[j];
        acc += v.x * w.x + v.y * w.y + v.z * w.z + v.w * w.w;
    }
    acc = warpSum(acc);
    if (lane == 0) g_slogit[row] = acc;
}

// softmax over S per b, apply mask -> g_ptr
__global__ void k_smax(const float* __restrict__ mask) {
    int b = blockIdx.x;
    int tid = threadIdx.x;     // 256
    int lane = tid & 31, wid = tid >> 5;
    __shared__ float red[8];
    float l = g_slogit[b * S + tid];
    float m = warpMax(l);
    if (lane == 0) red[wid] = m;
    __syncthreads();
    if (tid == 0) {
        float mm = red[0];
        #pragma unroll
        for (int i = 1; i < 8; i++) mm = fmaxf(mm, red[i]);
        red[0] = mm;
    }
    __syncthreads();
    float mx = red[0];
    __syncthreads();
    float e = expf(l - mx);
    float s = warpSum(e);
    if (lane == 0) red[wid] = s;
    __syncthreads();
    if (tid == 0) {
        float ss = 0.f;
        #pragma unroll
        for (int i = 0; i < 8; i++) ss += red[i];
        red[0] = ss;
    }
    __syncthreads();
    g_ptr[b * S + tid] = e / red[0] * mask[b * S + tid];
}

// D[b, 4t..4t+3] += sum_{s in 16-chunk} ptr[b,s]*lhs[b,s,4t..4t+3]
// grid (16, B), 192 threads, float4 per thread
__global__ void k_D(const float* __restrict__ lhs) {
    int sc = blockIdx.x, b = blockIdx.y;
    int tid = threadIdx.x;
    __shared__ float sp[16];
    if (tid < 16) sp[tid] = g_ptr[b * S + sc * 16 + tid];
    __syncthreads();
    const float4* base = (const float4*)(lhs + ((size_t)(b * S + sc * 16)) * H) + tid;
    float4 acc = make_float4(0.f, 0.f, 0.f, 0.f);
    #pragma unroll
    for (int s = 0; s < 16; s++) {
        float4 v = base[(size_t)s * (H / 4)];
        float w = sp[s];
        acc.x += w * v.x; acc.y += w * v.y; acc.z += w * v.z; acc.w += w * v.w;
    }
    float* dst = &g_D[b * H + tid * 4];
    atomicAdd(dst + 0, acc.x);
    atomicAdd(dst + 1, acc.y);
    atomicAdd(dst + 2, acc.z);
    atomicAdd(dst + 3, acc.w);
}

// fused partial GEMVs: D @ Wr (->Rlog), D @ Wc (->Clog), D @ Lw (->LD)
// grid (12 col-tiles, 4 h-chunks, B), 128 threads
__global__ void k_lin(const float* __restrict__ Wr, const float* __restrict__ Wc,
                      const float* __restrict__ Lw) {
    int tile = blockIdx.x, hc = blockIdx.y, b = blockIdx.z;
    int tid = threadIdx.x;
    int h0 = hc * 192;
    __shared__ float sD[192];
    if (tid < 128) sD[tid] = g_D[b * H + h0 + tid];
    if (tid < 64)  sD[128 + tid] = g_D[b * H + h0 + 128 + tid];
    __syncthreads();

    const float* W;
    float* dst;
    int ncols, col0, stride;
    if (tile < 5)       { W = Wr; dst = g_Rlog + b * (HOPS * NR); ncols = HOPS * NR; col0 = tile * 128;      stride = HOPS * NR; }
    else if (tile == 5) { W = Wc; dst = g_Clog + b * (HOPS * 2);  ncols = HOPS * 2;  col0 = 0;               stride = HOPS * 2; }
    else                { W = Lw; dst = g_LD   + b * H;           ncols = H;         col0 = (tile - 6) * 128; stride = H; }

    int col = col0 + tid;
    if (col >= ncols) return;
    const float* w = W + (size_t)h0 * stride + col;
    float acc = 0.f;
    #pragma unroll 8
    for (int h = 0; h < 192; h++) acc += sD[h] * w[(size_t)h * stride];
    atomicAdd(&dst[col], acc);
}

// softmax rels (200) + checks (2) per (b,hop)
__global__ void k_rsm() {
    int bh = blockIdx.x;
    int tid = threadIdx.x;   // 256
    int lane = tid & 31, wid = tid >> 5;
    __shared__ float red[8];
    float v = (tid < NR) ? g_Rlog[bh * NR + tid] : -INFINITY;
    float m = warpMax(v);
    if (lane == 0) red[wid] = m;
    __syncthreads();
    if (tid == 0) {
        float mm = red[0];
        #pragma unroll
        for (int i = 1; i < 8; i++) mm = fmaxf(mm, red[i]);
        red[0] = mm;
    }
    __syncthreads();
    float mx = red[0];
    __syncthreads();
    float e = (tid < NR) ? expf(v - mx) : 0.f;
    float s = warpSum(e);
    if (lane == 0) red[wid] = s;
    __syncthreads();
    if (tid == 0) {
        float ss = 0.f;
        #pragma unroll
        for (int i = 0; i < 8; i++) ss += red[i];
        red[0] = ss;
    }
    __syncthreads();
    if (tid < NR) g_R[bh * NR + tid] = e / red[0];
    if (tid == 0) {
        float c0 = g_Clog[bh * 2 + 0], c1 = g_Clog[bh * 2 + 1];
        float m2 = fmaxf(c0, c1);
        float e0 = expf(c0 - m2), e1 = expf(c1 - m2);
        float inv = 1.f / (e0 + e1);
        g_CS[bh * 2 + 0] = e0 * inv;
        g_CS[bh * 2 + 1] = e1 * inv;
    }
}

// scores[b,e] = LD[b,:] . sum_t EE[e,t,:]   (warp per e)
__global__ void k_scores(const float* __restrict__ EE) {
    __shared__ float4 sLD[B * 192];     // 24 KB
    const float4* LD4 = (const float4*)g_LD;
    for (int i = threadIdx.x; i < B * 192; i += blockDim.x) sLD[i] = LD4[i];
    __syncthreads();
    int warp = threadIdx.x >> 5, lane = threadIdx.x & 31;
    int e = blockIdx.x * 8 + warp;
    if (e >= NE) return;
    const float4* base = (const float4*)(EE + (size_t)e * 3072);
    float acc[B];
    #pragma unroll
    for (int b = 0; b < B; b++) acc[b] = 0.f;
    #pragma unroll
    for (int it = 0; it < 6; it++) {
        int j = lane + it * 32;
        float4 v0 = base[j], v1 = base[j + 192], v2 = base[j + 384], v3 = base[j + 576];
        float4 sx;
        sx.x = v0.x + v1.x + v2.x + v3.x;
        sx.y = v0.y + v1.y + v2.y + v3.y;
        sx.z = v0.z + v1.z + v2.z + v3.z;
        sx.w = v0.w + v1.w + v2.w + v3.w;
        #pragma unroll
        for (int b = 0; b < B; b++) {
            float4 l = sLD[b * 192 + j];
            acc[b] += sx.x * l.x + sx.y * l.y + sx.z * l.z + sx.w * l.w;
        }
    }
    #pragma unroll
    for (int b = 0; b < B; b++) {
        float v = warpSum(acc[b]);
        if (lane == 0) g_scores[b * NE + e] = v;
    }
}

// one hop: trip = R[b,hop,rel] * prev[head]; scatter-add by tail
__global__ void k_scatter(int hop, const float* __restrict__ init_ent,
                          const int* __restrict__ heads,
                          const int* __restrict__ rels,
                          const int* __restrict__ tails) {
    int idx = blockIdx.x * blockDim.x + threadIdx.x;
    if (idx >= B * NT) return;
    int b = idx / NT;
    int h = heads[idx];
    int r = rels[idx];
    int t = tails[idx];
    float prev;
    if (hop == 0) {
        prev = init_ent[b * NE + h];
    } else {
        int pbh = b * HOPS + hop - 1;
        float inv = 1.f / (g_sumacc[pbh] + 1e-6f);
        prev = g_walkraw[(size_t)pbh * NE + h] * inv;
    }
    float trip = g_R[(b * HOPS + hop) * NR + r] * prev;
    atomicAdd(&g_walkraw[(size_t)(b * HOPS + hop) * NE + t], trip);
}

// per-(b,hop) sum of walkraw -> g_sumacc (wide: grid (4,B))
__global__ void k_sum(int hop) {
    int c = blockIdx.x, b = blockIdx.y;
    int bh = b * HOPS + hop;
    int tid = threadIdx.x;  // 256
    int lane = tid & 31, wid = tid >> 5;
    __shared__ float red[8];
    const float* w = g_walkraw + (size_t)bh * NE + c * 5000;
    float s = 0.f;
    for (int e = tid; e < 5000; e += 256) s += w[e];
    s = warpSum(s);
    if (lane == 0) red[wid] = s;
    __syncthreads();
    if (tid == 0) {
        float ss = 0.f;
        #pragma unroll
        for (int i = 0; i < 8; i++) ss += red[i];
        atomicAdd(&g_sumacc[bh], ss);
    }
}

// pass 1: per-(b,hop) max of walk*scores  — grid (8, 24)
__global__ void k_f1() {
    int c = blockIdx.x, bh = blockIdx.y;
    int b = bh / HOPS;
    int tid = threadIdx.x;  // 256
    int lane = tid & 31, wid = tid >> 5;
    __shared__ float red[8];
    float inv = 1.f / (g_sumacc[bh] + 1e-6f);
    const float* wr = g_walkraw + (size_t)bh * NE + c * 2500;
    const float* sc = g_scores + (size_t)b * NE + c * 2500;
    float m = -1e30f;
    for (int e = tid; e < 2500; e += 256) m = fmaxf(m, wr[e] * inv * sc[e]);
    m = warpMax(m);
    if (lane == 0) red[wid] = m;
    __syncthreads();
    if (tid == 0) {
        float mm = red[0];
        #pragma unroll
        for (int i = 1; i < 8; i++) mm = fmaxf(mm, red[i]);
        atomicMaxF(&g_mx[bh], mm);
    }
}

// pass 2: exp -> g_ebuf, partial sums -> g_esum  — grid (8, 24)
__global__ void k_f2() {
    int c = blockIdx.x, bh = blockIdx.y;
    int b = bh / HOPS;
    int tid = threadIdx.x;  // 256
    int lane = tid & 31, wid = tid >> 5;
    __shared__ float red[8];
    float inv = 1.f / (g_sumacc[bh] + 1e-6f);
    float mx = g_mx[bh];
    const float* wr = g_walkraw + (size_t)bh * NE + c * 2500;
    const float* sc = g_scores + (size_t)b * NE + c * 2500;
    float* eb = g_ebuf + (size_t)bh * NE + c * 2500;
    float s = 0.f;
    for (int e = tid; e < 2500; e += 256) {
        float v = expf(wr[e] * inv * sc[e] - mx);
        eb[e] = v;
        s += v;
    }
    s = warpSum(s);
    if (lane == 0) red[wid] = s;
    __syncthreads();
    if (tid == 0) {
        float ss = 0.f;
        #pragma unroll
        for (int i = 0; i < 8; i++) ss += red[i];
        atomicAdd(&g_esum[bh], ss);
    }
}

// pass 3: combine -> out  — grid (8, 24)
__global__ void k_f3(float* __restrict__ out) {
    int c = blockIdx.x, bh = blockIdx.y;
    int tid = threadIdx.x;  // 256
    float inv = 1.f / (g_sumacc[bh] + 1e-6f);
    float einv = 1.f / g_esum[bh];
    float c0 = g_CS[bh * 2 + 0];
    float c1 = g_CS[bh * 2 + 1];
    const float* wr = g_walkraw + (size_t)bh * NE + c * 2500;
    const float* eb = g_ebuf + (size_t)bh * NE + c * 2500;
    float* o = out + (size_t)bh * NE + c * 2500;
    for (int e = tid; e < 2500; e += 256)
        o[e] = c0 * wr[e] * inv + c1 * eb[e] * einv;
}

// ---------------- launcher ----------------
extern "C" void kernel_launch(void* const* d_in, const int* in_sizes, int n_in,
                              void* d_out, int out_size) {
    const float* lhs      = (const float*)d_in[0];
    const float* mask     = (const float*)d_in[1];
    const float* init_ent = (const float*)d_in[2];
    const float* EE       = (const float*)d_in[3];
    // d_in[4] = W_q  (eliminated: constant term cancels in pointer softmax)
    const float* Wv       = (const float*)d_in[5];
    const float* Wp       = (const float*)d_in[6];
    const float* Wr       = (const float*)d_in[7];
    const float* Wc       = (const float*)d_in[8];
    const float* Lw       = (const float*)d_in[9];
    const int*   heads    = (const int*)d_in[10];
    const int*   rels     = (const int*)d_in[11];
    const int*   tails    = (const int*)d_in[12];
    float* out = (float*)d_out;

    k_init  <<<1875, 256>>>(Wv, Wp);                 // 1
    k_logit <<<64, 1024>>>(lhs);                     // 2
    k_smax  <<<B, 256>>>(mask);                      // 3
    { dim3 g(16, B); k_D <<<g, 192>>>(lhs); }        // 4  (profiled slot)
    { dim3 g(12, 4, B); k_lin <<<g, 128>>>(Wr, Wc, Lw); } // 5
    k_rsm   <<<B * HOPS, 256>>>();                   // 6
    k_scores<<<NE / 8, 256>>>(EE);                   // 7
    for (int hop = 0; hop < HOPS; hop++) {
        k_scatter<<<(B * NT + 255) / 256, 256>>>(hop, init_ent, heads, rels, tails);
        { dim3 g(4, B); k_sum<<<g, 256>>>(hop); }
    }
    { dim3 g(8, B * HOPS); k_f1<<<g, 256>>>(); }
    { dim3 g(8, B * HOPS); k_f2<<<g, 256>>>(); }
    { dim3 g(8, B * HOPS); k_f3<<<g, 256>>>(out); }
}